// round 12
// baseline (speedup 1.0000x reference)
#include <cuda_runtime.h>
#include <cuda_fp16.h>
#include <math.h>

// ---------------------------------------------------------------------------
// FractalDecoderV6 — fp16 m16n8k16 mma.sync (fp32 accumulate).
// R12: templated buffer counts (full unroll -> immediate LDS addresses),
// pair-packed B fragments (lds.128 feeds 2 MMAs).
// ---------------------------------------------------------------------------

typedef unsigned int u32;

#define Bn    16384
#define Tn    48
#define MROWS 128
#define NTHR  512

#define H_OFF    0        // h / feats: 128 x 256 halves (64KB), swizzled
#define G_OFF    65536    // g slice:   128 x 128 halves (32KB)
#define WB_OFF   98304    // 2 x 32KB weight buffers
#define BIAS_OFF 163840   // 6KB fp32 biases
#define SMEM_BYTES 169984

#define B1_B  0
#define B2_B  1024
#define BF1_B 2048
#define BF2_B 4096
#define BO_B  5120

// tape offsets (halves) — exact sizes
#define T_W1   0          // 12 kc (K=192)  -> 49152
#define T_W2   49152      // 16 kc (K=256)  -> 65536
#define T_SCAN 114688     // 4 x [G1 32768 | G2 32768] = 262144
#define T_WO   376832     // 16 kc (K=256)  -> 65536
#define NTAPE  442368
__device__ __align__(256) __half g_tape[NTAPE];

static __device__ __forceinline__ u32 s2u(const void* p){
    u32 a; asm("{ .reg .u64 t; cvta.to.shared.u64 t, %1; cvt.u32.u64 %0, t; }":"=r"(a):"l"(p)); return a;
}
static __device__ __forceinline__ void cp16u(u32 dst, const void* src){
    asm volatile("cp.async.cg.shared.global [%0], [%1], 16;" :: "r"(dst), "l"(src));
}
static __device__ __forceinline__ void cp_commit(){ asm volatile("cp.async.commit_group;"); }
static __device__ __forceinline__ void cp_wait0(){ asm volatile("cp.async.wait_group 0;"); }
static __device__ __forceinline__ void lds2u(u32 a, u32 &x, u32 &y){
    asm volatile("ld.shared.v2.b32 {%0,%1}, [%2];" : "=r"(x), "=r"(y) : "r"(a));
}
static __device__ __forceinline__ void lds4u(u32 a, u32 &x, u32 &y, u32 &z, u32 &w){
    asm volatile("ld.shared.v4.b32 {%0,%1,%2,%3}, [%4];"
        : "=r"(x), "=r"(y), "=r"(z), "=r"(w) : "r"(a));
}
static __device__ __forceinline__ u32 lds32u(u32 a){
    u32 v; asm volatile("ld.shared.b32 %0, [%1];" : "=r"(v) : "r"(a)); return v;
}
static __device__ __forceinline__ void sts32u(u32 a, u32 v){
    asm volatile("st.shared.b32 [%0], %1;" :: "r"(a), "r"(v) : "memory");
}
static __device__ __forceinline__ void sts16(u32 a, __half h){
    unsigned short b = __half_as_ushort(h);
    asm volatile("st.shared.b16 [%0], %1;" :: "r"(a), "h"(b) : "memory");
}
static __device__ __forceinline__ void stsf(u32 a, float v){
    asm volatile("st.shared.f32 [%0], %1;" :: "r"(a), "f"(v) : "memory");
}
static __device__ __forceinline__ float2 ldsf2(u32 a){
    float2 v; asm volatile("ld.shared.v2.f32 {%0,%1}, [%2];" : "=f"(v.x), "=f"(v.y) : "r"(a)); return v;
}

#define MMA16(d, A0,A1,A2,A3, B0,B1) \
    asm volatile("mma.sync.aligned.m16n8k16.row.col.f32.f16.f16.f32 " \
        "{%0,%1,%2,%3},{%4,%5,%6,%7},{%8,%9},{%0,%1,%2,%3};" \
        : "+f"((d)[0]),"+f"((d)[1]),"+f"((d)[2]),"+f"((d)[3]) \
        : "r"(A0),"r"(A1),"r"(A2),"r"(A3),"r"(B0),"r"(B1))

static __device__ __forceinline__ float gelu_e(float v){
    return 0.5f*v*(1.0f+erff(v*0.70710678118654752f));
}
static __device__ __forceinline__ float tanh_a(float x){
    float a = fabsf(x), em = expm1f(-2.0f*a);
    return copysignf(-em/(2.0f+em), x);
}
static __device__ __forceinline__ u32 haddr(u32 smb, int row, int col){
    return smb + H_OFF + (u32)(((row<<8) + (col ^ ((row&7)<<4)))<<1);
}
static __device__ __forceinline__ u32 gaddr(u32 smb, int row, int col){
    return smb + G_OFF + (u32)(((row<<7) + (col ^ ((row&7)<<4)))<<1);
}

// --------- prep: fp16-round weights + pack into PAIRED B-fragment tape ---------
// Unit per (kc, np, lane): 8 halves (16B). halves 0-3 -> nt=2np, m=0..3;
// halves 4-7 -> nt=2np+1, m=0..3; with k = kc*16 + 4*(lane&3) + m,
// n = nt*8 + (lane>>2). Linear: kc*(NTG*128) + np*256 + lane*8 + half.
__global__ void prep_tape(const float* __restrict__ W1, const float* __restrict__ W2,
                          const float* __restrict__ Wf1, const float* __restrict__ Wf2,
                          const float* __restrict__ Wo){
    int e = blockIdx.x*blockDim.x + threadIdx.x;
    if (e >= NTAPE) return;
    float v;
    if (e < T_W2){                       // 12 kc, NTG=32, K padded 161->192
        int q = e, kc = q>>12, r = q&4095, np = r>>8, lane = (r>>3)&31, hf = r&7;
        int nt = np*2 + (hf>>2), m = hf&3;
        int k = kc*16 + 4*(lane&3) + m, n = nt*8 + (lane>>2);
        v = (k < 161) ? W1[k*256 + n] : 0.0f;
    } else if (e < T_SCAN){              // 16 kc, NTG=32, K=256
        int q = e-T_W2, kc = q>>12, r = q&4095, np = r>>8, lane = (r>>3)&31, hf = r&7;
        int nt = np*2 + (hf>>2), m = hf&3;
        int k = kc*16 + 4*(lane&3) + m, n = nt*8 + (lane>>2);
        v = W2[k*256 + n];
    } else if (e < T_WO){
        int q = e-T_SCAN, s = q>>16, q2 = q&65535;
        if (q2 < 32768){  // G1: Wf1 slice s, NTG=16, 16 kc (K=256)
            int kc = q2>>11, r = q2&2047, np = r>>8, lane = (r>>3)&31, hf = r&7;
            int nt = np*2 + (hf>>2), m = hf&3;
            int k = kc*16 + 4*(lane&3) + m, n = s*128 + nt*8 + (lane>>2);
            v = Wf1[k*512 + n];
        } else {          // G2: Wf2 rows s*128..+128, NTG=32, 8 kc
            int q3 = q2-32768, kc = q3>>12, r = q3&4095, np = r>>8, lane = (r>>3)&31, hf = r&7;
            int nt = np*2 + (hf>>2), m = hf&3;
            int k = s*128 + kc*16 + 4*(lane&3) + m, n = nt*8 + (lane>>2);
            v = Wf2[k*256 + n];
        }
    } else {                             // Wo: 16 kc, NTG=32
        int q = e-T_WO, kc = q>>12, r = q&4095, np = r>>8, lane = (r>>3)&31, hf = r&7;
        int nt = np*2 + (hf>>2), m = hf&3;
        int k = kc*16 + 4*(lane&3) + m, n = nt*8 + (lane>>2);
        v = Wo[k*256 + n];
    }
    g_tape[e] = __float2half_rn(v);
}

// --------- streamed warp-MMA GEMM (templated: fully unrolled buffers) ---------
template<int NTW, int NBUF>
static __device__ __forceinline__ void gemmT(
    u32 a_sm, int astride, const __half* seg, const __half* nxt,
    float (*acc)[4], u32 wb, int &pc, int t, int wrow, int ntb, int lane)
{
    const int KCPB = (NTW==8) ? 4 : 8;
    const int NTG  = (NTW==8) ? 32 : 16;
    const int rl = lane>>2, li = lane&3;
    const int ntbh = ntb >> 1;
    #pragma unroll
    for (int ib = 0; ib < NBUF; ib++){
        cp_wait0(); __syncthreads();
        const char* src = (const char*)((ib+1 < NBUF) ? (seg + (size_t)(ib+1)*16384) : nxt);
        u32 dst = wb + (u32)(((pc+1)&1)<<15);
        #pragma unroll
        for (int i = 0; i < 4; i++)
            cp16u(dst + (u32)(t*16 + i*8192), src + t*16 + i*8192);
        cp_commit();
        u32 cur = wb + (u32)((pc&1)<<15);
        #pragma unroll
        for (int kk = 0; kk < KCPB; kk++){
            int kcg = ib*KCPB + kk;
            u32 a0[2], a1[2], a2[2], a3[2];
            #pragma unroll
            for (int mt = 0; mt < 2; mt++){
                int r1 = wrow + mt*16 + rl;
                int c  = (kcg*16 + 4*li) ^ (rl<<4);      // (r1&7)==rl
                u32 base = a_sm + (u32)((r1*astride + c)<<1);
                lds2u(base, a0[mt], a2[mt]);
                lds2u(base + (u32)(astride<<4), a1[mt], a3[mt]);   // +8 rows
            }
            #pragma unroll
            for (int ntp = 0; ntp < NTW/2; ntp++){
                u32 b0, b1v, b2, b3;
                lds4u(cur + (u32)(((kk*(NTG/2) + ntbh + ntp)*32 + lane)<<4),
                      b0, b1v, b2, b3);
                MMA16(acc[0*NTW+2*ntp],   a0[0], a1[0], a2[0], a3[0], b0, b1v);
                MMA16(acc[0*NTW+2*ntp+1], a0[0], a1[0], a2[0], a3[0], b2, b3);
                MMA16(acc[1*NTW+2*ntp],   a0[1], a1[1], a2[1], a3[1], b0, b1v);
                MMA16(acc[1*NTW+2*ntp+1], a0[1], a1[1], a2[1], a3[1], b2, b3);
            }
        }
        pc++;
    }
}

#define EPI8(...) \
    _Pragma("unroll") for (int mt = 0; mt < 2; mt++) \
    _Pragma("unroll") for (int hi = 0; hi < 2; hi++) \
    _Pragma("unroll") for (int nt = 0; nt < 8; nt++) { \
        int row = wrow2 + mt*16 + hi*8 + rl; \
        int col = wcol2 + nt*8 + cl; \
        float c0v = acc2[mt*8+nt][hi*2+0]; \
        float c1v = acc2[mt*8+nt][hi*2+1]; \
        __VA_ARGS__; \
    }

__global__ void __launch_bounds__(NTHR, 1)
fractal_h16(const float* __restrict__ x, const float* __restrict__ z,
            const float* __restrict__ tbl,
            const float* __restrict__ b1, const float* __restrict__ b2,
            const float* __restrict__ bf1, const float* __restrict__ bf2,
            const float* __restrict__ bo,
            const int* __restrict__ resolutions, const float* __restrict__ freqs,
            float* __restrict__ out)
{
    extern __shared__ char smc[];
    const u32 smb = s2u(smc);
    const u32 wb  = smb + WB_OFF;
    const int t = threadIdx.x, w = t>>5, lane = t&31;
    const int r0 = blockIdx.x * MROWS;
    const int rl = lane>>2, cl = 2*(lane&3);
    const int wrow2 = (w&3)*32, ntb2 = (w>>2)*8, wcol2 = (w>>2)*64;
    const int wrow1 = (w&3)*32, ntb1 = (w>>2)*4, wcol1 = (w>>2)*32;

    // biases -> SMEM
    if (t < 256){
        stsf(smb+BIAS_OFF+B1_B + t*4, b1[t]);
        stsf(smb+BIAS_OFF+B2_B + t*4, b2[t]);
        stsf(smb+BIAS_OFF+BF2_B + t*4, bf2[t]);
        stsf(smb+BIAS_OFF+BO_B + t*4, bo[t]);
    }
    stsf(smb+BIAS_OFF+BF1_B + t*4, bf1[t]);

    // prime: W1 buffer 0
    {
        const char* src = (const char*)(g_tape + T_W1);
        #pragma unroll
        for (int i = 0; i < 4; i++)
            cp16u(wb + (u32)(t*16 + i*8192), src + t*16 + i*8192);
        cp_commit();
    }
    int pc = 0;

    // ---------- feature stage -> H region (fp16, K padded to 192) ----------
    {
        int row = t >> 2, sub = t & 3, gr = r0 + row;
        float xn = fminf(fmaxf(x[gr], 0.0f), 1.0f);
        #define FWH(c, v) sts16(smb + H_OFF + (u32)((((row)<<8) + ((c) ^ ((row&7)<<4)))<<1), __float2half_rn(v))
        if (sub == 0) FWH(0, xn);
        float aarg = 6.2831855f * xn;
        #pragma unroll
        for (int q = 0; q < 8; q++){
            int fi = sub*8 + q;
            double s, c; sincos((double)(aarg * freqs[fi]), &s, &c);
            FWH(1+fi, (float)s); FWH(33+fi, (float)c);
        }
        #pragma unroll
        for (int lq = 0; lq < 2; lq++){
            int lv = sub*2 + lq;
            int R = resolutions[lv];
            float tf = xn * (float)(R-1);
            int i0 = (int)floorf(tf), i1 = min(i0+1, R-1);
            float wt = tf - (float)i0;
            unsigned lt = (unsigned)(lv * 19349663);
            int h0 = (int)((((unsigned)i0*73856093u)^lt)&16383u);
            int h1 = (int)((((unsigned)i1*73856093u)^lt)&16383u);
            const float* e0 = tbl + ((size_t)lv*16384 + h0)*8;
            const float* e1 = tbl + ((size_t)lv*16384 + h1)*8;
            #pragma unroll
            for (int e = 0; e < 8; e++)
                FWH(65 + lv*8 + e, e0[e]*(1.0f-wt) + e1[e]*wt);
        }
        #pragma unroll
        for (int q = 0; q < 8; q++)
            FWH(129 + sub*8 + q, z[(size_t)gr*32 + sub*8 + q]);
        for (int c = 161 + sub; c < 192; c += 4)
            FWH(c, 0.0f);
        #undef FWH
    }

    float acc2[16][4];
    #pragma unroll
    for (int i = 0; i < 16; i++) for (int j = 0; j < 4; j++) acc2[i][j] = 0.0f;

    // ---------------- GEMM0: feats @ W1 (K=192, 3 buffers) ----------------
    gemmT<8,3>(smb+H_OFF, 256, g_tape+T_W1, g_tape+T_W2, acc2, wb, pc, t, wrow2, ntb2, lane);
    __syncthreads();   // H overwrite vs lagging readers
    EPI8(
        float2 bb = ldsf2(smb+BIAS_OFF+B1_B + col*4);
        __half2 hh = __floats2half2_rn(gelu_e(c0v + bb.x), gelu_e(c1v + bb.y));
        sts32u(haddr(smb, row, col), *(u32*)&hh);
    );

    // ---------------- h = gelu(h1 @ W2 + b2) ----------------
    #pragma unroll
    for (int i = 0; i < 16; i++) for (int j = 0; j < 4; j++) acc2[i][j] = 0.0f;
    gemmT<8,4>(smb+H_OFF, 256, g_tape+T_W2, g_tape+T_SCAN, acc2, wb, pc, t, wrow2, ntb2, lane);
    __syncthreads();
    EPI8(
        float2 bb = ldsf2(smb+BIAS_OFF+B2_B + col*4);
        __half2 hh = __floats2half2_rn(gelu_e(c0v + bb.x), gelu_e(c1v + bb.y));
        sts32u(haddr(smb, row, col), *(u32*)&hh);
    );

    // ---------------- 48-step scan ----------------
    #pragma unroll 1
    for (int step = 0; step < Tn; step++){
        #pragma unroll 1
        for (int s = 0; s < 4; s++){
            const __half* g1s = g_tape + T_SCAN + (size_t)s*65536;
            const __half* g2s = g1s + 32768;
            float acc1[8][4];
            #pragma unroll
            for (int i = 0; i < 8; i++) for (int j = 0; j < 4; j++) acc1[i][j] = 0.0f;
            gemmT<4,2>(smb+H_OFF, 256, g1s, g2s, acc1, wb, pc, t, wrow1, ntb1, lane);
            // G1 epi: g = gelu(. + bf1 slice) -> G region (fp16)
            #pragma unroll
            for (int mt = 0; mt < 2; mt++)
            #pragma unroll
            for (int hi = 0; hi < 2; hi++)
            #pragma unroll
            for (int nt = 0; nt < 4; nt++){
                int row = wrow1 + mt*16 + hi*8 + rl;
                int col = wcol1 + nt*8 + cl;
                float2 bb = ldsf2(smb+BIAS_OFF+BF1_B + (s*128+col)*4);
                __half2 hh = __floats2half2_rn(gelu_e(acc1[mt*4+nt][hi*2+0] + bb.x),
                                               gelu_e(acc1[mt*4+nt][hi*2+1] + bb.y));
                sts32u(gaddr(smb, row, col), *(u32*)&hh);
            }
            if (s == 0){
                #pragma unroll
                for (int i = 0; i < 16; i++) for (int j = 0; j < 4; j++) acc2[i][j] = 0.0f;
            }
            const __half* nxt = (s < 3) ? (g_tape + T_SCAN + (size_t)(s+1)*65536)
                               : (step < Tn-1 ? g_tape + T_SCAN : g_tape + T_WO);
            gemmT<8,2>(smb+G_OFF, 128, g2s, nxt, acc2, wb, pc, t, wrow2, ntb2, lane);
        }
        // blend epi: u = tanh(. + bf2); h = 0.5h + 0.5u
        EPI8(
            float2 bb = ldsf2(smb+BIAS_OFF+BF2_B + col*4);
            float u0 = tanh_a(c0v + bb.x);
            float u1 = tanh_a(c1v + bb.y);
            u32 ha = haddr(smb, row, col);
            u32 ob = lds32u(ha);
            float2 of = __half22float2(*(__half2*)&ob);
            __half2 hh = __floats2half2_rn(0.5f*of.x + 0.5f*u0, 0.5f*of.y + 0.5f*u1);
            sts32u(ha, *(u32*)&hh);
        );
    }

    // ---------------- final: out = h @ Wo + bo ----------------
    #pragma unroll
    for (int i = 0; i < 16; i++) for (int j = 0; j < 4; j++) acc2[i][j] = 0.0f;
    gemmT<8,4>(smb+H_OFF, 256, g_tape+T_WO, g_tape+T_W1, acc2, wb, pc, t, wrow2, ntb2, lane);
    EPI8(
        float2 bb = ldsf2(smb+BIAS_OFF+BO_B + col*4);
        float2 vv = make_float2(c0v + bb.x, c1v + bb.y);
        *(float2*)&out[(size_t)(r0+row)*256 + col] = vv;
    );
    cp_wait0();
}

extern "C" void kernel_launch(void* const* d_in, const int* in_sizes, int n_in,
                              void* d_out, int out_size)
{
    (void)out_size;
    const float *x=0,*z=0,*tbl=0,*W1=0,*b1=0,*W2=0,*b2=0,*Wf1=0,*bf1=0,*Wf2=0,*bf2=0,*Wo=0,*bo=0,*frq=0;
    const int* res=0;
    int c65536=0, c131072=0, c256=0;
    for (int i = 0; i < n_in; i++){
        const void* p = d_in[i];
        switch (in_sizes[i]){
            case 16384:   x   = (const float*)p; break;
            case 524288:  z   = (const float*)p; break;
            case 1048576: tbl = (const float*)p; break;
            case 41216:   W1  = (const float*)p; break;
            case 512:     bf1 = (const float*)p; break;
            case 8:       res = (const int*)p;   break;
            case 32:      frq = (const float*)p; break;
            case 65536:   if (c65536++  == 0) W2  = (const float*)p; else Wo  = (const float*)p; break;
            case 131072:  if (c131072++ == 0) Wf1 = (const float*)p; else Wf2 = (const float*)p; break;
            case 256:
                switch (c256++){
                    case 0: b1 = (const float*)p; break;
                    case 1: b2 = (const float*)p; break;
                    case 2: bf2 = (const float*)p; break;
                    default: bo = (const float*)p; break;
                }
                break;
            default: break;
        }
    }
    float* out = (float*)d_out;

    prep_tape<<<(NTAPE + 255)/256, 256>>>(W1, W2, Wf1, Wf2, Wo);

    cudaFuncSetAttribute(fractal_h16, cudaFuncAttributeMaxDynamicSharedMemorySize, SMEM_BYTES);
    fractal_h16<<<Bn/MROWS, NTHR, SMEM_BYTES>>>(x, z, tbl, b1, b2, bf1, bf2, bo, res, frq, out);
}

// round 13
// speedup vs baseline: 1.0755x; 1.0755x over previous
#include <cuda_runtime.h>
#include <cuda_fp16.h>
#include <math.h>

// ---------------------------------------------------------------------------
// FractalDecoderV6 — fp16 m16n8k16 mma.sync (fp32 accumulate).
// R13: R11 engine, occupancy 2 CTAs/SM (64 rows/CTA, 256 thr, 256 CTAs).
// ---------------------------------------------------------------------------

typedef unsigned int u32;

#define Bn    16384
#define Tn    48
#define MROWS 64
#define NTHR  256

#define H_OFF    0        // h / feats: 64 x 256 halves (32KB), swizzled
#define G_OFF    32768    // g slice:   64 x 128 halves (16KB)
#define WB_OFF   49152    // 2 x 16KB weight buffers
#define BIAS_OFF 81920    // 6KB fp32 biases
#define SMEM_BYTES 88064

#define B1_B  0
#define B2_B  1024
#define BF1_B 2048
#define BF2_B 4096
#define BO_B  5120

// tape offsets (halves) — exact sizes (same layout/content as R11)
#define T_W1   0          // 12 kc (K=192)  -> 49152
#define T_W2   49152      // 16 kc (K=256)  -> 65536
#define T_SCAN 114688     // 4 x [G1 32768 | G2 32768] = 262144
#define T_WO   376832     // 16 kc (K=256)  -> 65536
#define NTAPE  442368
__device__ __align__(256) __half g_tape[NTAPE];

static __device__ __forceinline__ u32 s2u(const void* p){
    u32 a; asm("{ .reg .u64 t; cvta.to.shared.u64 t, %1; cvt.u32.u64 %0, t; }":"=r"(a):"l"(p)); return a;
}
static __device__ __forceinline__ void cp16u(u32 dst, const void* src){
    asm volatile("cp.async.cg.shared.global [%0], [%1], 16;" :: "r"(dst), "l"(src));
}
static __device__ __forceinline__ void cp_commit(){ asm volatile("cp.async.commit_group;"); }
static __device__ __forceinline__ void cp_wait0(){ asm volatile("cp.async.wait_group 0;"); }
static __device__ __forceinline__ void lds2u(u32 a, u32 &x, u32 &y){
    asm volatile("ld.shared.v2.b32 {%0,%1}, [%2];" : "=r"(x), "=r"(y) : "r"(a));
}
static __device__ __forceinline__ u32 lds32u(u32 a){
    u32 v; asm volatile("ld.shared.b32 %0, [%1];" : "=r"(v) : "r"(a)); return v;
}
static __device__ __forceinline__ void sts32u(u32 a, u32 v){
    asm volatile("st.shared.b32 [%0], %1;" :: "r"(a), "r"(v) : "memory");
}
static __device__ __forceinline__ void sts16(u32 a, __half h){
    unsigned short b = __half_as_ushort(h);
    asm volatile("st.shared.b16 [%0], %1;" :: "r"(a), "h"(b) : "memory");
}
static __device__ __forceinline__ void stsf(u32 a, float v){
    asm volatile("st.shared.f32 [%0], %1;" :: "r"(a), "f"(v) : "memory");
}
static __device__ __forceinline__ float2 ldsf2(u32 a){
    float2 v; asm volatile("ld.shared.v2.f32 {%0,%1}, [%2];" : "=f"(v.x), "=f"(v.y) : "r"(a)); return v;
}

#define MMA16(d, A0,A1,A2,A3, B0,B1) \
    asm volatile("mma.sync.aligned.m16n8k16.row.col.f32.f16.f16.f32 " \
        "{%0,%1,%2,%3},{%4,%5,%6,%7},{%8,%9},{%0,%1,%2,%3};" \
        : "+f"((d)[0]),"+f"((d)[1]),"+f"((d)[2]),"+f"((d)[3]) \
        : "r"(A0),"r"(A1),"r"(A2),"r"(A3),"r"(B0),"r"(B1))

static __device__ __forceinline__ float gelu_e(float v){
    return 0.5f*v*(1.0f+erff(v*0.70710678118654752f));
}
static __device__ __forceinline__ float tanh_a(float x){
    float a = fabsf(x), em = expm1f(-2.0f*a);
    return copysignf(-em/(2.0f+em), x);
}
static __device__ __forceinline__ u32 haddr(u32 smb, int row, int col){
    return smb + H_OFF + (u32)(((row<<8) + (col ^ ((row&7)<<4)))<<1);
}
static __device__ __forceinline__ u32 gaddr(u32 smb, int row, int col){
    return smb + G_OFF + (u32)(((row<<7) + (col ^ ((row&7)<<4)))<<1);
}

// --------- prep: fp16-round weights + pack into B-fragment tape (R11 layout) ---------
__global__ void prep_tape(const float* __restrict__ W1, const float* __restrict__ W2,
                          const float* __restrict__ Wf1, const float* __restrict__ Wf2,
                          const float* __restrict__ Wo){
    int e = blockIdx.x*blockDim.x + threadIdx.x;
    if (e >= NTAPE) return;
    float v;
    if (e < T_W2){                       // 12 kc, K padded 161->192
        int q = e, kc = q>>12, r = q&4095, nt = r>>7, lane = (r>>2)&31, m = r&3;
        int k = kc*16 + 4*(lane&3) + m, n = nt*8 + (lane>>2);
        v = (k < 161) ? W1[k*256 + n] : 0.0f;
    } else if (e < T_SCAN){              // 16 kc, K=256
        int q = e-T_W2, kc = q>>12, r = q&4095, nt = r>>7, lane = (r>>2)&31, m = r&3;
        int k = kc*16 + 4*(lane&3) + m, n = nt*8 + (lane>>2);
        v = W2[k*256 + n];
    } else if (e < T_WO){
        int q = e-T_SCAN, s = q>>16, q2 = q&65535;
        if (q2 < 32768){  // G1: Wf1 slice s, N=128 (16 nt), K=256
            int kc = q2>>11, r = q2&2047, nt = r>>7, lane = (r>>2)&31, m = r&3;
            int k = kc*16 + 4*(lane&3) + m, n = s*128 + nt*8 + (lane>>2);
            v = Wf1[k*512 + n];
        } else {          // G2: Wf2 rows s*128..+128, N=256 (32 nt)
            int q3 = q2-32768, kc = q3>>12, r = q3&4095, nt = r>>7, lane = (r>>2)&31, m = r&3;
            int k = s*128 + kc*16 + 4*(lane&3) + m, n = nt*8 + (lane>>2);
            v = Wf2[k*256 + n];
        }
    } else {                             // Wo: 16 kc, K=256
        int q = e-T_WO, kc = q>>12, r = q&4095, nt = r>>7, lane = (r>>2)&31, m = r&3;
        int k = kc*16 + 4*(lane&3) + m, n = nt*8 + (lane>>2);
        v = Wo[k*256 + n];
    }
    g_tape[e] = __float2half_rn(v);
}

// --------- streamed warp-MMA GEMM (R11 style; 16KB buffers) ---------
template<int NTW>
static __device__ __forceinline__ void gemmT(
    u32 a_sm, int astride, int nbuf, const __half* seg, const __half* nxt,
    float (*acc)[4], u32 wb, int &pc, int t, int wrow, int ntb, int lane)
{
    const int KCPB = (NTW==8) ? 2 : 4;     // kc per 16KB buffer
    const int NTG  = (NTW==8) ? 32 : 16;
    const int rl = lane>>2, li = lane&3;
    for (int ib = 0; ib < nbuf; ib++){
        cp_wait0(); __syncthreads();
        const char* src = (const char*)((ib+1 < nbuf) ? (seg + (size_t)(ib+1)*8192) : nxt);
        u32 dst = wb + (u32)(((pc+1)&1)<<14);
        #pragma unroll
        for (int i = 0; i < 4; i++)
            cp16u(dst + (u32)(t*16 + i*4096), src + t*16 + i*4096);
        cp_commit();
        u32 cur = wb + (u32)((pc&1)<<14);
        #pragma unroll
        for (int kk = 0; kk < KCPB; kk++){
            int kcg = ib*KCPB + kk;
            u32 a0[2], a1[2], a2[2], a3[2];
            #pragma unroll
            for (int mt = 0; mt < 2; mt++){
                int r1 = wrow + mt*16 + rl;
                int c  = (kcg*16 + 4*li) ^ (rl<<4);      // (r1&7)==rl
                u32 base = a_sm + (u32)((r1*astride + c)<<1);
                lds2u(base, a0[mt], a2[mt]);
                lds2u(base + (u32)(astride<<4), a1[mt], a3[mt]);   // +8 rows
            }
            #pragma unroll
            for (int nt = 0; nt < NTW; nt++){
                u32 b0, b1v;
                lds2u(cur + (u32)(((kk*NTG + ntb + nt)*32 + lane)<<3), b0, b1v);
                MMA16(acc[0*NTW+nt], a0[0], a1[0], a2[0], a3[0], b0, b1v);
                MMA16(acc[1*NTW+nt], a0[1], a1[1], a2[1], a3[1], b0, b1v);
            }
        }
        pc++;
    }
}

#define EPI8(...) \
    _Pragma("unroll") for (int mt = 0; mt < 2; mt++) \
    _Pragma("unroll") for (int hi = 0; hi < 2; hi++) \
    _Pragma("unroll") for (int nt = 0; nt < 8; nt++) { \
        int row = wrow2 + mt*16 + hi*8 + rl; \
        int col = wcol2 + nt*8 + cl; \
        float c0v = acc2[mt*8+nt][hi*2+0]; \
        float c1v = acc2[mt*8+nt][hi*2+1]; \
        __VA_ARGS__; \
    }

__global__ void __launch_bounds__(NTHR, 2)
fractal_h16(const float* __restrict__ x, const float* __restrict__ z,
            const float* __restrict__ tbl,
            const float* __restrict__ b1, const float* __restrict__ b2,
            const float* __restrict__ bf1, const float* __restrict__ bf2,
            const float* __restrict__ bo,
            const int* __restrict__ resolutions, const float* __restrict__ freqs,
            float* __restrict__ out)
{
    extern __shared__ char smc[];
    const u32 smb = s2u(smc);
    const u32 wb  = smb + WB_OFF;
    const int t = threadIdx.x, w = t>>5, lane = t&31;
    const int r0 = blockIdx.x * MROWS;
    const int rl = lane>>2, cl = 2*(lane&3);
    // 8 warps: 2 (M) x 4 (N) grid
    const int wrow2 = (w&1)*32, ntb2 = (w>>1)*8, wcol2 = (w>>1)*64;
    const int wrow1 = (w&1)*32, ntb1 = (w>>1)*4, wcol1 = (w>>1)*32;

    // biases -> SMEM
    stsf(smb+BIAS_OFF+B1_B  + t*4, b1[t]);
    stsf(smb+BIAS_OFF+B2_B  + t*4, b2[t]);
    stsf(smb+BIAS_OFF+BF2_B + t*4, bf2[t]);
    stsf(smb+BIAS_OFF+BO_B  + t*4, bo[t]);
    stsf(smb+BIAS_OFF+BF1_B + t*4, bf1[t]);
    stsf(smb+BIAS_OFF+BF1_B + (t+256)*4, bf1[t+256]);

    // prime: W1 buffer 0 (first 16KB)
    {
        const char* src = (const char*)(g_tape + T_W1);
        #pragma unroll
        for (int i = 0; i < 4; i++)
            cp16u(wb + (u32)(t*16 + i*4096), src + t*16 + i*4096);
        cp_commit();
    }
    int pc = 0;

    // ---------- feature stage -> H region (fp16, K padded to 192) ----------
    {
        int row = t >> 2, sub = t & 3, gr = r0 + row;
        float xn = fminf(fmaxf(x[gr], 0.0f), 1.0f);
        #define FWH(c, v) sts16(smb + H_OFF + (u32)((((row)<<8) + ((c) ^ ((row&7)<<4)))<<1), __float2half_rn(v))
        if (sub == 0) FWH(0, xn);
        float aarg = 6.2831855f * xn;
        #pragma unroll
        for (int q = 0; q < 8; q++){
            int fi = sub*8 + q;
            double s, c; sincos((double)(aarg * freqs[fi]), &s, &c);
            FWH(1+fi, (float)s); FWH(33+fi, (float)c);
        }
        #pragma unroll
        for (int lq = 0; lq < 2; lq++){
            int lv = sub*2 + lq;
            int R = resolutions[lv];
            float tf = xn * (float)(R-1);
            int i0 = (int)floorf(tf), i1 = min(i0+1, R-1);
            float wt = tf - (float)i0;
            unsigned lt = (unsigned)(lv * 19349663);
            int h0 = (int)((((unsigned)i0*73856093u)^lt)&16383u);
            int h1 = (int)((((unsigned)i1*73856093u)^lt)&16383u);
            const float* e0 = tbl + ((size_t)lv*16384 + h0)*8;
            const float* e1 = tbl + ((size_t)lv*16384 + h1)*8;
            #pragma unroll
            for (int e = 0; e < 8; e++)
                FWH(65 + lv*8 + e, e0[e]*(1.0f-wt) + e1[e]*wt);
        }
        #pragma unroll
        for (int q = 0; q < 8; q++)
            FWH(129 + sub*8 + q, z[(size_t)gr*32 + sub*8 + q]);
        for (int c = 161 + sub; c < 192; c += 4)
            FWH(c, 0.0f);
        #undef FWH
    }

    float acc2[16][4];
    #pragma unroll
    for (int i = 0; i < 16; i++) for (int j = 0; j < 4; j++) acc2[i][j] = 0.0f;

    // ---------------- GEMM0: feats @ W1 (K=192, 6 buffers) ----------------
    gemmT<8>(smb+H_OFF, 256, 6, g_tape+T_W1, g_tape+T_W2, acc2, wb, pc, t, wrow2, ntb2, lane);
    __syncthreads();   // H overwrite vs lagging readers
    EPI8(
        float2 bb = ldsf2(smb+BIAS_OFF+B1_B + col*4);
        __half2 hh = __floats2half2_rn(gelu_e(c0v + bb.x), gelu_e(c1v + bb.y));
        sts32u(haddr(smb, row, col), *(u32*)&hh);
    );

    // ---------------- h = gelu(h1 @ W2 + b2) (8 buffers) ----------------
    #pragma unroll
    for (int i = 0; i < 16; i++) for (int j = 0; j < 4; j++) acc2[i][j] = 0.0f;
    gemmT<8>(smb+H_OFF, 256, 8, g_tape+T_W2, g_tape+T_SCAN, acc2, wb, pc, t, wrow2, ntb2, lane);
    __syncthreads();
    EPI8(
        float2 bb = ldsf2(smb+BIAS_OFF+B2_B + col*4);
        __half2 hh = __floats2half2_rn(gelu_e(c0v + bb.x), gelu_e(c1v + bb.y));
        sts32u(haddr(smb, row, col), *(u32*)&hh);
    );

    // ---------------- 48-step scan ----------------
    #pragma unroll 1
    for (int step = 0; step < Tn; step++){
        #pragma unroll 1
        for (int s = 0; s < 4; s++){
            const __half* g1s = g_tape + T_SCAN + (size_t)s*65536;
            const __half* g2s = g1s + 32768;
            float acc1[8][4];
            #pragma unroll
            for (int i = 0; i < 8; i++) for (int j = 0; j < 4; j++) acc1[i][j] = 0.0f;
            gemmT<4>(smb+H_OFF, 256, 4, g1s, g2s, acc1, wb, pc, t, wrow1, ntb1, lane);
            // G1 epi: g = gelu(. + bf1 slice) -> G region (fp16)
            #pragma unroll
            for (int mt = 0; mt < 2; mt++)
            #pragma unroll
            for (int hi = 0; hi < 2; hi++)
            #pragma unroll
            for (int nt = 0; nt < 4; nt++){
                int row = wrow1 + mt*16 + hi*8 + rl;
                int col = wcol1 + nt*8 + cl;
                float2 bb = ldsf2(smb+BIAS_OFF+BF1_B + (s*128+col)*4);
                __half2 hh = __floats2half2_rn(gelu_e(acc1[mt*4+nt][hi*2+0] + bb.x),
                                               gelu_e(acc1[mt*4+nt][hi*2+1] + bb.y));
                sts32u(gaddr(smb, row, col), *(u32*)&hh);
            }
            if (s == 0){
                #pragma unroll
                for (int i = 0; i < 16; i++) for (int j = 0; j < 4; j++) acc2[i][j] = 0.0f;
            }
            const __half* nxt = (s < 3) ? (g_tape + T_SCAN + (size_t)(s+1)*65536)
                               : (step < Tn-1 ? g_tape + T_SCAN : g_tape + T_WO);
            gemmT<8>(smb+G_OFF, 128, 4, g2s, nxt, acc2, wb, pc, t, wrow2, ntb2, lane);
        }
        // blend epi: u = tanh(. + bf2); h = 0.5h + 0.5u
        EPI8(
            float2 bb = ldsf2(smb+BIAS_OFF+BF2_B + col*4);
            float u0 = tanh_a(c0v + bb.x);
            float u1 = tanh_a(c1v + bb.y);
            u32 ha = haddr(smb, row, col);
            u32 ob = lds32u(ha);
            float2 of = __half22float2(*(__half2*)&ob);
            __half2 hh = __floats2half2_rn(0.5f*of.x + 0.5f*u0, 0.5f*of.y + 0.5f*u1);
            sts32u(ha, *(u32*)&hh);
        );
    }

    // ---------------- final: out = h @ Wo + bo (8 buffers) ----------------
    #pragma unroll
    for (int i = 0; i < 16; i++) for (int j = 0; j < 4; j++) acc2[i][j] = 0.0f;
    gemmT<8>(smb+H_OFF, 256, 8, g_tape+T_WO, g_tape+T_W1, acc2, wb, pc, t, wrow2, ntb2, lane);
    EPI8(
        float2 bb = ldsf2(smb+BIAS_OFF+BO_B + col*4);
        float2 vv = make_float2(c0v + bb.x, c1v + bb.y);
        *(float2*)&out[(size_t)(r0+row)*256 + col] = vv;
    );
    cp_wait0();
}

extern "C" void kernel_launch(void* const* d_in, const int* in_sizes, int n_in,
                              void* d_out, int out_size)
{
    (void)out_size;
    const float *x=0,*z=0,*tbl=0,*W1=0,*b1=0,*W2=0,*b2=0,*Wf1=0,*bf1=0,*Wf2=0,*bf2=0,*Wo=0,*bo=0,*frq=0;
    const int* res=0;
    int c65536=0, c131072=0, c256=0;
    for (int i = 0; i < n_in; i++){
        const void* p = d_in[i];
        switch (in_sizes[i]){
            case 16384:   x   = (const float*)p; break;
            case 524288:  z   = (const float*)p; break;
            case 1048576: tbl = (const float*)p; break;
            case 41216:   W1  = (const float*)p; break;
            case 512:     bf1 = (const float*)p; break;
            case 8:       res = (const int*)p;   break;
            case 32:      frq = (const float*)p; break;
            case 65536:   if (c65536++  == 0) W2  = (const float*)p; else Wo  = (const float*)p; break;
            case 131072:  if (c131072++ == 0) Wf1 = (const float*)p; else Wf2 = (const float*)p; break;
            case 256:
                switch (c256++){
                    case 0: b1 = (const float*)p; break;
                    case 1: b2 = (const float*)p; break;
                    case 2: bf2 = (const float*)p; break;
                    default: bo = (const float*)p; break;
                }
                break;
            default: break;
        }
    }
    float* out = (float*)d_out;

    prep_tape<<<(NTAPE + 255)/256, 256>>>(W1, W2, Wf1, Wf2, Wo);

    cudaFuncSetAttribute(fractal_h16, cudaFuncAttributeMaxDynamicSharedMemorySize, SMEM_BYTES);
    fractal_h16<<<Bn/MROWS, NTHR, SMEM_BYTES>>>(x, z, tbl, b1, b2, bf1, bf2, bo, res, frq, out);
}

// round 14
// speedup vs baseline: 1.3007x; 1.2094x over previous
#include <cuda_runtime.h>
#include <cuda_fp16.h>
#include <math.h>

// ---------------------------------------------------------------------------
// FractalDecoderV6 — fp16 m16n8k16 mma.sync (fp32 accumulate).
// R14: R11 base (128 rows/CTA, 512 thr, 32KB buffers, runtime buffer loop)
//      + pair-packed B fragments (lds.128) + MUFU-based fast tanh.
// ---------------------------------------------------------------------------

typedef unsigned int u32;

#define Bn    16384
#define Tn    48
#define MROWS 128
#define NTHR  512

#define H_OFF    0        // h / feats: 128 x 256 halves (64KB), swizzled
#define G_OFF    65536    // g slice:   128 x 128 halves (32KB)
#define WB_OFF   98304    // 2 x 32KB weight buffers
#define BIAS_OFF 163840   // 6KB fp32 biases
#define SMEM_BYTES 169984

#define B1_B  0
#define B2_B  1024
#define BF1_B 2048
#define BF2_B 4096
#define BO_B  5120

// tape offsets (halves) — exact sizes
#define T_W1   0          // 12 kc (K=192)  -> 49152
#define T_W2   49152      // 16 kc (K=256)  -> 65536
#define T_SCAN 114688     // 4 x [G1 32768 | G2 32768] = 262144
#define T_WO   376832     // 16 kc (K=256)  -> 65536
#define NTAPE  442368
__device__ __align__(256) __half g_tape[NTAPE];

static __device__ __forceinline__ u32 s2u(const void* p){
    u32 a; asm("{ .reg .u64 t; cvta.to.shared.u64 t, %1; cvt.u32.u64 %0, t; }":"=r"(a):"l"(p)); return a;
}
static __device__ __forceinline__ void cp16u(u32 dst, const void* src){
    asm volatile("cp.async.cg.shared.global [%0], [%1], 16;" :: "r"(dst), "l"(src));
}
static __device__ __forceinline__ void cp_commit(){ asm volatile("cp.async.commit_group;"); }
static __device__ __forceinline__ void cp_wait0(){ asm volatile("cp.async.wait_group 0;"); }
static __device__ __forceinline__ void lds2u(u32 a, u32 &x, u32 &y){
    asm volatile("ld.shared.v2.b32 {%0,%1}, [%2];" : "=r"(x), "=r"(y) : "r"(a));
}
static __device__ __forceinline__ void lds4u(u32 a, u32 &x, u32 &y, u32 &z, u32 &w){
    asm volatile("ld.shared.v4.b32 {%0,%1,%2,%3}, [%4];"
        : "=r"(x), "=r"(y), "=r"(z), "=r"(w) : "r"(a));
}
static __device__ __forceinline__ u32 lds32u(u32 a){
    u32 v; asm volatile("ld.shared.b32 %0, [%1];" : "=r"(v) : "r"(a)); return v;
}
static __device__ __forceinline__ void sts32u(u32 a, u32 v){
    asm volatile("st.shared.b32 [%0], %1;" :: "r"(a), "r"(v) : "memory");
}
static __device__ __forceinline__ void sts16(u32 a, __half h){
    unsigned short b = __half_as_ushort(h);
    asm volatile("st.shared.b16 [%0], %1;" :: "r"(a), "h"(b) : "memory");
}
static __device__ __forceinline__ void stsf(u32 a, float v){
    asm volatile("st.shared.f32 [%0], %1;" :: "r"(a), "f"(v) : "memory");
}
static __device__ __forceinline__ float2 ldsf2(u32 a){
    float2 v; asm volatile("ld.shared.v2.f32 {%0,%1}, [%2];" : "=f"(v.x), "=f"(v.y) : "r"(a)); return v;
}

#define MMA16(d, A0,A1,A2,A3, B0,B1) \
    asm volatile("mma.sync.aligned.m16n8k16.row.col.f32.f16.f16.f32 " \
        "{%0,%1,%2,%3},{%4,%5,%6,%7},{%8,%9},{%0,%1,%2,%3};" \
        : "+f"((d)[0]),"+f"((d)[1]),"+f"((d)[2]),"+f"((d)[3]) \
        : "r"(A0),"r"(A1),"r"(A2),"r"(A3),"r"(B0),"r"(B1))

static __device__ __forceinline__ float gelu_e(float v){
    return 0.5f*v*(1.0f+erff(v*0.70710678118654752f));
}
// tanh via MUFU ex2: tanh(x) = 1 - 2/(2^(2x*log2e)+1). rel err ~5e-7.
static __device__ __forceinline__ float tanh_f(float x){
    float e;
    asm("ex2.approx.ftz.f32 %0, %1;" : "=f"(e) : "f"(x * 2.8853900817779268f));
    return 1.0f - __fdividef(2.0f, e + 1.0f);
}
static __device__ __forceinline__ u32 haddr(u32 smb, int row, int col){
    return smb + H_OFF + (u32)(((row<<8) + (col ^ ((row&7)<<4)))<<1);
}
static __device__ __forceinline__ u32 gaddr(u32 smb, int row, int col){
    return smb + G_OFF + (u32)(((row<<7) + (col ^ ((row&7)<<4)))<<1);
}

// --------- prep: fp16-round weights + PAIR-packed B-fragment tape ---------
// 16B unit per (kc, np, lane): halves 0-3 -> nt=2np m=0..3, halves 4-7 -> nt=2np+1.
// k = kc*16 + 4*(lane&3) + m, n = nt*8 + (lane>>2).
// Linear (halves): kc*(NTG*128) + np*256 + lane*8 + hf.
__global__ void prep_tape(const float* __restrict__ W1, const float* __restrict__ W2,
                          const float* __restrict__ Wf1, const float* __restrict__ Wf2,
                          const float* __restrict__ Wo){
    int e = blockIdx.x*blockDim.x + threadIdx.x;
    if (e >= NTAPE) return;
    float v;
    if (e < T_W2){                       // 12 kc, NTG=32, K padded 161->192
        int q = e, kc = q>>12, r = q&4095, np = r>>8, lane = (r>>3)&31, hf = r&7;
        int nt = np*2 + (hf>>2), m = hf&3;
        int k = kc*16 + 4*(lane&3) + m, n = nt*8 + (lane>>2);
        v = (k < 161) ? W1[k*256 + n] : 0.0f;
    } else if (e < T_SCAN){              // 16 kc, NTG=32, K=256
        int q = e-T_W2, kc = q>>12, r = q&4095, np = r>>8, lane = (r>>3)&31, hf = r&7;
        int nt = np*2 + (hf>>2), m = hf&3;
        int k = kc*16 + 4*(lane&3) + m, n = nt*8 + (lane>>2);
        v = W2[k*256 + n];
    } else if (e < T_WO){
        int q = e-T_SCAN, s = q>>16, q2 = q&65535;
        if (q2 < 32768){  // G1: Wf1 slice s, NTG=16, 16 kc (K=256)
            int kc = q2>>11, r = q2&2047, np = r>>8, lane = (r>>3)&31, hf = r&7;
            int nt = np*2 + (hf>>2), m = hf&3;
            int k = kc*16 + 4*(lane&3) + m, n = s*128 + nt*8 + (lane>>2);
            v = Wf1[k*512 + n];
        } else {          // G2: Wf2 rows s*128..+128, NTG=32, 8 kc
            int q3 = q2-32768, kc = q3>>12, r = q3&4095, np = r>>8, lane = (r>>3)&31, hf = r&7;
            int nt = np*2 + (hf>>2), m = hf&3;
            int k = s*128 + kc*16 + 4*(lane&3) + m, n = nt*8 + (lane>>2);
            v = Wf2[k*256 + n];
        }
    } else {                             // Wo: 16 kc, NTG=32
        int q = e-T_WO, kc = q>>12, r = q&4095, np = r>>8, lane = (r>>3)&31, hf = r&7;
        int nt = np*2 + (hf>>2), m = hf&3;
        int k = kc*16 + 4*(lane&3) + m, n = nt*8 + (lane>>2);
        v = Wo[k*256 + n];
    }
    g_tape[e] = __float2half_rn(v);
}

// --------- streamed warp-MMA GEMM (runtime buffer loop; lds.128 B pairs) ---------
template<int NTW>
static __device__ __forceinline__ void gemmT(
    u32 a_sm, int astride, int nbuf, const __half* seg, const __half* nxt,
    float (*acc)[4], u32 wb, int &pc, int t, int wrow, int ntb, int lane)
{
    const int KCPB = (NTW==8) ? 4 : 8;   // kc per 32KB buffer
    const int NTG  = (NTW==8) ? 32 : 16;
    const int rl = lane>>2, li = lane&3;
    const int ntbh = ntb >> 1;
    for (int ib = 0; ib < nbuf; ib++){
        cp_wait0(); __syncthreads();
        const char* src = (const char*)((ib+1 < nbuf) ? (seg + (size_t)(ib+1)*16384) : nxt);
        u32 dst = wb + (u32)(((pc+1)&1)<<15);
        #pragma unroll
        for (int i = 0; i < 4; i++)
            cp16u(dst + (u32)(t*16 + i*8192), src + t*16 + i*8192);
        cp_commit();
        u32 cur = wb + (u32)((pc&1)<<15);
        #pragma unroll
        for (int kk = 0; kk < KCPB; kk++){
            int kcg = ib*KCPB + kk;
            u32 a0[2], a1[2], a2[2], a3[2];
            #pragma unroll
            for (int mt = 0; mt < 2; mt++){
                int r1 = wrow + mt*16 + rl;
                int c  = (kcg*16 + 4*li) ^ (rl<<4);      // (r1&7)==rl
                u32 base = a_sm + (u32)((r1*astride + c)<<1);
                lds2u(base, a0[mt], a2[mt]);
                lds2u(base + (u32)(astride<<4), a1[mt], a3[mt]);   // +8 rows
            }
            #pragma unroll
            for (int ntp = 0; ntp < NTW/2; ntp++){
                u32 b0, b1v, b2, b3;
                lds4u(cur + (u32)(((kk*(NTG/2) + ntbh + ntp)*32 + lane)<<4),
                      b0, b1v, b2, b3);
                MMA16(acc[0*NTW+2*ntp],   a0[0], a1[0], a2[0], a3[0], b0, b1v);
                MMA16(acc[0*NTW+2*ntp+1], a0[0], a1[0], a2[0], a3[0], b2, b3);
                MMA16(acc[1*NTW+2*ntp],   a0[1], a1[1], a2[1], a3[1], b0, b1v);
                MMA16(acc[1*NTW+2*ntp+1], a0[1], a1[1], a2[1], a3[1], b2, b3);
            }
        }
        pc++;
    }
}

#define EPI8(...) \
    _Pragma("unroll") for (int mt = 0; mt < 2; mt++) \
    _Pragma("unroll") for (int hi = 0; hi < 2; hi++) \
    _Pragma("unroll") for (int nt = 0; nt < 8; nt++) { \
        int row = wrow2 + mt*16 + hi*8 + rl; \
        int col = wcol2 + nt*8 + cl; \
        float c0v = acc2[mt*8+nt][hi*2+0]; \
        float c1v = acc2[mt*8+nt][hi*2+1]; \
        __VA_ARGS__; \
    }

__global__ void __launch_bounds__(NTHR, 1)
fractal_h16(const float* __restrict__ x, const float* __restrict__ z,
            const float* __restrict__ tbl,
            const float* __restrict__ b1, const float* __restrict__ b2,
            const float* __restrict__ bf1, const float* __restrict__ bf2,
            const float* __restrict__ bo,
            const int* __restrict__ resolutions, const float* __restrict__ freqs,
            float* __restrict__ out)
{
    extern __shared__ char smc[];
    const u32 smb = s2u(smc);
    const u32 wb  = smb + WB_OFF;
    const int t = threadIdx.x, w = t>>5, lane = t&31;
    const int r0 = blockIdx.x * MROWS;
    const int rl = lane>>2, cl = 2*(lane&3);
    const int wrow2 = (w&3)*32, ntb2 = (w>>2)*8, wcol2 = (w>>2)*64;
    const int wrow1 = (w&3)*32, ntb1 = (w>>2)*4, wcol1 = (w>>2)*32;

    // biases -> SMEM
    if (t < 256){
        stsf(smb+BIAS_OFF+B1_B + t*4, b1[t]);
        stsf(smb+BIAS_OFF+B2_B + t*4, b2[t]);
        stsf(smb+BIAS_OFF+BF2_B + t*4, bf2[t]);
        stsf(smb+BIAS_OFF+BO_B + t*4, bo[t]);
    }
    stsf(smb+BIAS_OFF+BF1_B + t*4, bf1[t]);

    // prime: W1 buffer 0
    {
        const char* src = (const char*)(g_tape + T_W1);
        #pragma unroll
        for (int i = 0; i < 4; i++)
            cp16u(wb + (u32)(t*16 + i*8192), src + t*16 + i*8192);
        cp_commit();
    }
    int pc = 0;

    // ---------- feature stage -> H region (fp16, K padded to 192) ----------
    {
        int row = t >> 2, sub = t & 3, gr = r0 + row;
        float xn = fminf(fmaxf(x[gr], 0.0f), 1.0f);
        #define FWH(c, v) sts16(smb + H_OFF + (u32)((((row)<<8) + ((c) ^ ((row&7)<<4)))<<1), __float2half_rn(v))
        if (sub == 0) FWH(0, xn);
        float aarg = 6.2831855f * xn;
        #pragma unroll
        for (int q = 0; q < 8; q++){
            int fi = sub*8 + q;
            double s, c; sincos((double)(aarg * freqs[fi]), &s, &c);
            FWH(1+fi, (float)s); FWH(33+fi, (float)c);
        }
        #pragma unroll
        for (int lq = 0; lq < 2; lq++){
            int lv = sub*2 + lq;
            int R = resolutions[lv];
            float tf = xn * (float)(R-1);
            int i0 = (int)floorf(tf), i1 = min(i0+1, R-1);
            float wt = tf - (float)i0;
            unsigned lt = (unsigned)(lv * 19349663);
            int h0 = (int)((((unsigned)i0*73856093u)^lt)&16383u);
            int h1 = (int)((((unsigned)i1*73856093u)^lt)&16383u);
            const float* e0 = tbl + ((size_t)lv*16384 + h0)*8;
            const float* e1 = tbl + ((size_t)lv*16384 + h1)*8;
            #pragma unroll
            for (int e = 0; e < 8; e++)
                FWH(65 + lv*8 + e, e0[e]*(1.0f-wt) + e1[e]*wt);
        }
        #pragma unroll
        for (int q = 0; q < 8; q++)
            FWH(129 + sub*8 + q, z[(size_t)gr*32 + sub*8 + q]);
        for (int c = 161 + sub; c < 192; c += 4)
            FWH(c, 0.0f);
        #undef FWH
    }

    float acc2[16][4];
    #pragma unroll
    for (int i = 0; i < 16; i++) for (int j = 0; j < 4; j++) acc2[i][j] = 0.0f;

    // ---------------- GEMM0: feats @ W1 (K=192, 3 buffers) ----------------
    gemmT<8>(smb+H_OFF, 256, 3, g_tape+T_W1, g_tape+T_W2, acc2, wb, pc, t, wrow2, ntb2, lane);
    __syncthreads();   // H overwrite vs lagging readers
    EPI8(
        float2 bb = ldsf2(smb+BIAS_OFF+B1_B + col*4);
        __half2 hh = __floats2half2_rn(gelu_e(c0v + bb.x), gelu_e(c1v + bb.y));
        sts32u(haddr(smb, row, col), *(u32*)&hh);
    );

    // ---------------- h = gelu(h1 @ W2 + b2) ----------------
    #pragma unroll
    for (int i = 0; i < 16; i++) for (int j = 0; j < 4; j++) acc2[i][j] = 0.0f;
    gemmT<8>(smb+H_OFF, 256, 4, g_tape+T_W2, g_tape+T_SCAN, acc2, wb, pc, t, wrow2, ntb2, lane);
    __syncthreads();
    EPI8(
        float2 bb = ldsf2(smb+BIAS_OFF+B2_B + col*4);
        __half2 hh = __floats2half2_rn(gelu_e(c0v + bb.x), gelu_e(c1v + bb.y));
        sts32u(haddr(smb, row, col), *(u32*)&hh);
    );

    // ---------------- 48-step scan ----------------
    #pragma unroll 1
    for (int step = 0; step < Tn; step++){
        #pragma unroll 1
        for (int s = 0; s < 4; s++){
            const __half* g1s = g_tape + T_SCAN + (size_t)s*65536;
            const __half* g2s = g1s + 32768;
            float acc1[8][4];
            #pragma unroll
            for (int i = 0; i < 8; i++) for (int j = 0; j < 4; j++) acc1[i][j] = 0.0f;
            gemmT<4>(smb+H_OFF, 256, 2, g1s, g2s, acc1, wb, pc, t, wrow1, ntb1, lane);
            // G1 epi: g = gelu(. + bf1 slice) -> G region (fp16)
            #pragma unroll
            for (int mt = 0; mt < 2; mt++)
            #pragma unroll
            for (int hi = 0; hi < 2; hi++)
            #pragma unroll
            for (int nt = 0; nt < 4; nt++){
                int row = wrow1 + mt*16 + hi*8 + rl;
                int col = wcol1 + nt*8 + cl;
                float2 bb = ldsf2(smb+BIAS_OFF+BF1_B + (s*128+col)*4);
                __half2 hh = __floats2half2_rn(gelu_e(acc1[mt*4+nt][hi*2+0] + bb.x),
                                               gelu_e(acc1[mt*4+nt][hi*2+1] + bb.y));
                sts32u(gaddr(smb, row, col), *(u32*)&hh);
            }
            if (s == 0){
                #pragma unroll
                for (int i = 0; i < 16; i++) for (int j = 0; j < 4; j++) acc2[i][j] = 0.0f;
            }
            const __half* nxt = (s < 3) ? (g_tape + T_SCAN + (size_t)(s+1)*65536)
                               : (step < Tn-1 ? g_tape + T_SCAN : g_tape + T_WO);
            gemmT<8>(smb+G_OFF, 128, 2, g2s, nxt, acc2, wb, pc, t, wrow2, ntb2, lane);
        }
        // blend epi: u = tanh(. + bf2); h = 0.5h + 0.5u
        EPI8(
            float2 bb = ldsf2(smb+BIAS_OFF+BF2_B + col*4);
            float u0 = tanh_f(c0v + bb.x);
            float u1 = tanh_f(c1v + bb.y);
            u32 ha = haddr(smb, row, col);
            u32 ob = lds32u(ha);
            float2 of = __half22float2(*(__half2*)&ob);
            __half2 hh = __floats2half2_rn(0.5f*of.x + 0.5f*u0, 0.5f*of.y + 0.5f*u1);
            sts32u(ha, *(u32*)&hh);
        );
    }

    // ---------------- final: out = h @ Wo + bo ----------------
    #pragma unroll
    for (int i = 0; i < 16; i++) for (int j = 0; j < 4; j++) acc2[i][j] = 0.0f;
    gemmT<8>(smb+H_OFF, 256, 4, g_tape+T_WO, g_tape+T_W1, acc2, wb, pc, t, wrow2, ntb2, lane);
    EPI8(
        float2 bb = ldsf2(smb+BIAS_OFF+BO_B + col*4);
        float2 vv = make_float2(c0v + bb.x, c1v + bb.y);
        *(float2*)&out[(size_t)(r0+row)*256 + col] = vv;
    );
    cp_wait0();
}

extern "C" void kernel_launch(void* const* d_in, const int* in_sizes, int n_in,
                              void* d_out, int out_size)
{
    (void)out_size;
    const float *x=0,*z=0,*tbl=0,*W1=0,*b1=0,*W2=0,*b2=0,*Wf1=0,*bf1=0,*Wf2=0,*bf2=0,*Wo=0,*bo=0,*frq=0;
    const int* res=0;
    int c65536=0, c131072=0, c256=0;
    for (int i = 0; i < n_in; i++){
        const void* p = d_in[i];
        switch (in_sizes[i]){
            case 16384:   x   = (const float*)p; break;
            case 524288:  z   = (const float*)p; break;
            case 1048576: tbl = (const float*)p; break;
            case 41216:   W1  = (const float*)p; break;
            case 512:     bf1 = (const float*)p; break;
            case 8:       res = (const int*)p;   break;
            case 32:      frq = (const float*)p; break;
            case 65536:   if (c65536++  == 0) W2  = (const float*)p; else Wo  = (const float*)p; break;
            case 131072:  if (c131072++ == 0) Wf1 = (const float*)p; else Wf2 = (const float*)p; break;
            case 256:
                switch (c256++){
                    case 0: b1 = (const float*)p; break;
                    case 1: b2 = (const float*)p; break;
                    case 2: bf2 = (const float*)p; break;
                    default: bo = (const float*)p; break;
                }
                break;
            default: break;
        }
    }
    float* out = (float*)d_out;

    prep_tape<<<(NTAPE + 255)/256, 256>>>(W1, W2, Wf1, Wf2, Wo);

    cudaFuncSetAttribute(fractal_h16, cudaFuncAttributeMaxDynamicSharedMemorySize, SMEM_BYTES);
    fractal_h16<<<Bn/MROWS, NTHR, SMEM_BYTES>>>(x, z, tbl, b1, b2, bf1, bf2, bo, res, frq, out);
}

// round 15
// speedup vs baseline: 1.4101x; 1.0841x over previous
#include <cuda_runtime.h>
#include <cuda_fp16.h>
#include <math.h>

// ---------------------------------------------------------------------------
// FractalDecoderV6 — fp16 m16n8k16 mma.sync (fp32 accumulate).
// R15: R14 + branch-free A&S-7.1.26 gelu (MUFU rcp/ex2, ~13 instr, err<2e-7).
// ---------------------------------------------------------------------------

typedef unsigned int u32;

#define Bn    16384
#define Tn    48
#define MROWS 128
#define NTHR  512

#define H_OFF    0        // h / feats: 128 x 256 halves (64KB), swizzled
#define G_OFF    65536    // g slice:   128 x 128 halves (32KB)
#define WB_OFF   98304    // 2 x 32KB weight buffers
#define BIAS_OFF 163840   // 6KB fp32 biases
#define SMEM_BYTES 169984

#define B1_B  0
#define B2_B  1024
#define BF1_B 2048
#define BF2_B 4096
#define BO_B  5120

// tape offsets (halves) — exact sizes
#define T_W1   0          // 12 kc (K=192)  -> 49152
#define T_W2   49152      // 16 kc (K=256)  -> 65536
#define T_SCAN 114688     // 4 x [G1 32768 | G2 32768] = 262144
#define T_WO   376832     // 16 kc (K=256)  -> 65536
#define NTAPE  442368
__device__ __align__(256) __half g_tape[NTAPE];

static __device__ __forceinline__ u32 s2u(const void* p){
    u32 a; asm("{ .reg .u64 t; cvta.to.shared.u64 t, %1; cvt.u32.u64 %0, t; }":"=r"(a):"l"(p)); return a;
}
static __device__ __forceinline__ void cp16u(u32 dst, const void* src){
    asm volatile("cp.async.cg.shared.global [%0], [%1], 16;" :: "r"(dst), "l"(src));
}
static __device__ __forceinline__ void cp_commit(){ asm volatile("cp.async.commit_group;"); }
static __device__ __forceinline__ void cp_wait0(){ asm volatile("cp.async.wait_group 0;"); }
static __device__ __forceinline__ void lds2u(u32 a, u32 &x, u32 &y){
    asm volatile("ld.shared.v2.b32 {%0,%1}, [%2];" : "=r"(x), "=r"(y) : "r"(a));
}
static __device__ __forceinline__ void lds4u(u32 a, u32 &x, u32 &y, u32 &z, u32 &w){
    asm volatile("ld.shared.v4.b32 {%0,%1,%2,%3}, [%4];"
        : "=r"(x), "=r"(y), "=r"(z), "=r"(w) : "r"(a));
}
static __device__ __forceinline__ u32 lds32u(u32 a){
    u32 v; asm volatile("ld.shared.b32 %0, [%1];" : "=r"(v) : "r"(a)); return v;
}
static __device__ __forceinline__ void sts32u(u32 a, u32 v){
    asm volatile("st.shared.b32 [%0], %1;" :: "r"(a), "r"(v) : "memory");
}
static __device__ __forceinline__ void sts16(u32 a, __half h){
    unsigned short b = __half_as_ushort(h);
    asm volatile("st.shared.b16 [%0], %1;" :: "r"(a), "h"(b) : "memory");
}
static __device__ __forceinline__ void stsf(u32 a, float v){
    asm volatile("st.shared.f32 [%0], %1;" :: "r"(a), "f"(v) : "memory");
}
static __device__ __forceinline__ float2 ldsf2(u32 a){
    float2 v; asm volatile("ld.shared.v2.f32 {%0,%1}, [%2];" : "=f"(v.x), "=f"(v.y) : "r"(a)); return v;
}

#define MMA16(d, A0,A1,A2,A3, B0,B1) \
    asm volatile("mma.sync.aligned.m16n8k16.row.col.f32.f16.f16.f32 " \
        "{%0,%1,%2,%3},{%4,%5,%6,%7},{%8,%9},{%0,%1,%2,%3};" \
        : "+f"((d)[0]),"+f"((d)[1]),"+f"((d)[2]),"+f"((d)[3]) \
        : "r"(A0),"r"(A1),"r"(A2),"r"(A3),"r"(B0),"r"(B1))

// Branch-free gelu: 0.5x(1+erf(x/sqrt2)); erf via A&S 7.1.26 (|err|<=1.5e-7),
// MUFU rcp.approx + ex2.approx. ~13 instructions, no divergence.
static __device__ __forceinline__ float gelu_f(float x){
    float z = fabsf(x) * 0.70710678118654752f;
    float t;
    asm("rcp.approx.ftz.f32 %0, %1;" : "=f"(t) : "f"(fmaf(0.3275911f, z, 1.0f)));
    float p = fmaf(1.061405429f, t, -1.453152027f);
    p = fmaf(p, t, 1.421413741f);
    p = fmaf(p, t, -0.284496736f);
    p = fmaf(p, t, 0.254829592f);
    p = p * t;
    float e;
    asm("ex2.approx.ftz.f32 %0, %1;" : "=f"(e) : "f"(z * z * -1.4426950408889634f));
    float er = fmaf(-p, e, 1.0f);          // erf(|x|/sqrt2) in [0,1)
    float s  = copysignf(er, x);
    return fmaf(0.5f * x, s, 0.5f * x);    // 0.5x(1+erf_signed)
}
// tanh via MUFU ex2: tanh(x) = 1 - 2/(2^(2x*log2e)+1). rel err ~5e-7.
static __device__ __forceinline__ float tanh_f(float x){
    float e;
    asm("ex2.approx.ftz.f32 %0, %1;" : "=f"(e) : "f"(x * 2.8853900817779268f));
    return 1.0f - __fdividef(2.0f, e + 1.0f);
}
static __device__ __forceinline__ u32 haddr(u32 smb, int row, int col){
    return smb + H_OFF + (u32)(((row<<8) + (col ^ ((row&7)<<4)))<<1);
}
static __device__ __forceinline__ u32 gaddr(u32 smb, int row, int col){
    return smb + G_OFF + (u32)(((row<<7) + (col ^ ((row&7)<<4)))<<1);
}

// --------- prep: fp16-round weights + PAIR-packed B-fragment tape ---------
// 16B unit per (kc, np, lane): halves 0-3 -> nt=2np m=0..3, halves 4-7 -> nt=2np+1.
// k = kc*16 + 4*(lane&3) + m, n = nt*8 + (lane>>2).
// Linear (halves): kc*(NTG*128) + np*256 + lane*8 + hf.
__global__ void prep_tape(const float* __restrict__ W1, const float* __restrict__ W2,
                          const float* __restrict__ Wf1, const float* __restrict__ Wf2,
                          const float* __restrict__ Wo){
    int e = blockIdx.x*blockDim.x + threadIdx.x;
    if (e >= NTAPE) return;
    float v;
    if (e < T_W2){                       // 12 kc, NTG=32, K padded 161->192
        int q = e, kc = q>>12, r = q&4095, np = r>>8, lane = (r>>3)&31, hf = r&7;
        int nt = np*2 + (hf>>2), m = hf&3;
        int k = kc*16 + 4*(lane&3) + m, n = nt*8 + (lane>>2);
        v = (k < 161) ? W1[k*256 + n] : 0.0f;
    } else if (e < T_SCAN){              // 16 kc, NTG=32, K=256
        int q = e-T_W2, kc = q>>12, r = q&4095, np = r>>8, lane = (r>>3)&31, hf = r&7;
        int nt = np*2 + (hf>>2), m = hf&3;
        int k = kc*16 + 4*(lane&3) + m, n = nt*8 + (lane>>2);
        v = W2[k*256 + n];
    } else if (e < T_WO){
        int q = e-T_SCAN, s = q>>16, q2 = q&65535;
        if (q2 < 32768){  // G1: Wf1 slice s, NTG=16, 16 kc (K=256)
            int kc = q2>>11, r = q2&2047, np = r>>8, lane = (r>>3)&31, hf = r&7;
            int nt = np*2 + (hf>>2), m = hf&3;
            int k = kc*16 + 4*(lane&3) + m, n = s*128 + nt*8 + (lane>>2);
            v = Wf1[k*512 + n];
        } else {          // G2: Wf2 rows s*128..+128, NTG=32, 8 kc
            int q3 = q2-32768, kc = q3>>12, r = q3&4095, np = r>>8, lane = (r>>3)&31, hf = r&7;
            int nt = np*2 + (hf>>2), m = hf&3;
            int k = s*128 + kc*16 + 4*(lane&3) + m, n = nt*8 + (lane>>2);
            v = Wf2[k*256 + n];
        }
    } else {                             // Wo: 16 kc, NTG=32
        int q = e-T_WO, kc = q>>12, r = q&4095, np = r>>8, lane = (r>>3)&31, hf = r&7;
        int nt = np*2 + (hf>>2), m = hf&3;
        int k = kc*16 + 4*(lane&3) + m, n = nt*8 + (lane>>2);
        v = Wo[k*256 + n];
    }
    g_tape[e] = __float2half_rn(v);
}

// --------- streamed warp-MMA GEMM (runtime buffer loop; lds.128 B pairs) ---------
template<int NTW>
static __device__ __forceinline__ void gemmT(
    u32 a_sm, int astride, int nbuf, const __half* seg, const __half* nxt,
    float (*acc)[4], u32 wb, int &pc, int t, int wrow, int ntb, int lane)
{
    const int KCPB = (NTW==8) ? 4 : 8;   // kc per 32KB buffer
    const int NTG  = (NTW==8) ? 32 : 16;
    const int rl = lane>>2, li = lane&3;
    const int ntbh = ntb >> 1;
    for (int ib = 0; ib < nbuf; ib++){
        cp_wait0(); __syncthreads();
        const char* src = (const char*)((ib+1 < nbuf) ? (seg + (size_t)(ib+1)*16384) : nxt);
        u32 dst = wb + (u32)(((pc+1)&1)<<15);
        #pragma unroll
        for (int i = 0; i < 4; i++)
            cp16u(dst + (u32)(t*16 + i*8192), src + t*16 + i*8192);
        cp_commit();
        u32 cur = wb + (u32)((pc&1)<<15);
        #pragma unroll
        for (int kk = 0; kk < KCPB; kk++){
            int kcg = ib*KCPB + kk;
            u32 a0[2], a1[2], a2[2], a3[2];
            #pragma unroll
            for (int mt = 0; mt < 2; mt++){
                int r1 = wrow + mt*16 + rl;
                int c  = (kcg*16 + 4*li) ^ (rl<<4);      // (r1&7)==rl
                u32 base = a_sm + (u32)((r1*astride + c)<<1);
                lds2u(base, a0[mt], a2[mt]);
                lds2u(base + (u32)(astride<<4), a1[mt], a3[mt]);   // +8 rows
            }
            #pragma unroll
            for (int ntp = 0; ntp < NTW/2; ntp++){
                u32 b0, b1v, b2, b3;
                lds4u(cur + (u32)(((kk*(NTG/2) + ntbh + ntp)*32 + lane)<<4),
                      b0, b1v, b2, b3);
                MMA16(acc[0*NTW+2*ntp],   a0[0], a1[0], a2[0], a3[0], b0, b1v);
                MMA16(acc[0*NTW+2*ntp+1], a0[0], a1[0], a2[0], a3[0], b2, b3);
                MMA16(acc[1*NTW+2*ntp],   a0[1], a1[1], a2[1], a3[1], b0, b1v);
                MMA16(acc[1*NTW+2*ntp+1], a0[1], a1[1], a2[1], a3[1], b2, b3);
            }
        }
        pc++;
    }
}

#define EPI8(...) \
    _Pragma("unroll") for (int mt = 0; mt < 2; mt++) \
    _Pragma("unroll") for (int hi = 0; hi < 2; hi++) \
    _Pragma("unroll") for (int nt = 0; nt < 8; nt++) { \
        int row = wrow2 + mt*16 + hi*8 + rl; \
        int col = wcol2 + nt*8 + cl; \
        float c0v = acc2[mt*8+nt][hi*2+0]; \
        float c1v = acc2[mt*8+nt][hi*2+1]; \
        __VA_ARGS__; \
    }

__global__ void __launch_bounds__(NTHR, 1)
fractal_h16(const float* __restrict__ x, const float* __restrict__ z,
            const float* __restrict__ tbl,
            const float* __restrict__ b1, const float* __restrict__ b2,
            const float* __restrict__ bf1, const float* __restrict__ bf2,
            const float* __restrict__ bo,
            const int* __restrict__ resolutions, const float* __restrict__ freqs,
            float* __restrict__ out)
{
    extern __shared__ char smc[];
    const u32 smb = s2u(smc);
    const u32 wb  = smb + WB_OFF;
    const int t = threadIdx.x, w = t>>5, lane = t&31;
    const int r0 = blockIdx.x * MROWS;
    const int rl = lane>>2, cl = 2*(lane&3);
    const int wrow2 = (w&3)*32, ntb2 = (w>>2)*8, wcol2 = (w>>2)*64;
    const int wrow1 = (w&3)*32, ntb1 = (w>>2)*4, wcol1 = (w>>2)*32;

    // biases -> SMEM
    if (t < 256){
        stsf(smb+BIAS_OFF+B1_B + t*4, b1[t]);
        stsf(smb+BIAS_OFF+B2_B + t*4, b2[t]);
        stsf(smb+BIAS_OFF+BF2_B + t*4, bf2[t]);
        stsf(smb+BIAS_OFF+BO_B + t*4, bo[t]);
    }
    stsf(smb+BIAS_OFF+BF1_B + t*4, bf1[t]);

    // prime: W1 buffer 0
    {
        const char* src = (const char*)(g_tape + T_W1);
        #pragma unroll
        for (int i = 0; i < 4; i++)
            cp16u(wb + (u32)(t*16 + i*8192), src + t*16 + i*8192);
        cp_commit();
    }
    int pc = 0;

    // ---------- feature stage -> H region (fp16, K padded to 192) ----------
    {
        int row = t >> 2, sub = t & 3, gr = r0 + row;
        float xn = fminf(fmaxf(x[gr], 0.0f), 1.0f);
        #define FWH(c, v) sts16(smb + H_OFF + (u32)((((row)<<8) + ((c) ^ ((row&7)<<4)))<<1), __float2half_rn(v))
        if (sub == 0) FWH(0, xn);
        float aarg = 6.2831855f * xn;
        #pragma unroll
        for (int q = 0; q < 8; q++){
            int fi = sub*8 + q;
            double s, c; sincos((double)(aarg * freqs[fi]), &s, &c);
            FWH(1+fi, (float)s); FWH(33+fi, (float)c);
        }
        #pragma unroll
        for (int lq = 0; lq < 2; lq++){
            int lv = sub*2 + lq;
            int R = resolutions[lv];
            float tf = xn * (float)(R-1);
            int i0 = (int)floorf(tf), i1 = min(i0+1, R-1);
            float wt = tf - (float)i0;
            unsigned lt = (unsigned)(lv * 19349663);
            int h0 = (int)((((unsigned)i0*73856093u)^lt)&16383u);
            int h1 = (int)((((unsigned)i1*73856093u)^lt)&16383u);
            const float* e0 = tbl + ((size_t)lv*16384 + h0)*8;
            const float* e1 = tbl + ((size_t)lv*16384 + h1)*8;
            #pragma unroll
            for (int e = 0; e < 8; e++)
                FWH(65 + lv*8 + e, e0[e]*(1.0f-wt) + e1[e]*wt);
        }
        #pragma unroll
        for (int q = 0; q < 8; q++)
            FWH(129 + sub*8 + q, z[(size_t)gr*32 + sub*8 + q]);
        for (int c = 161 + sub; c < 192; c += 4)
            FWH(c, 0.0f);
        #undef FWH
    }

    float acc2[16][4];
    #pragma unroll
    for (int i = 0; i < 16; i++) for (int j = 0; j < 4; j++) acc2[i][j] = 0.0f;

    // ---------------- GEMM0: feats @ W1 (K=192, 3 buffers) ----------------
    gemmT<8>(smb+H_OFF, 256, 3, g_tape+T_W1, g_tape+T_W2, acc2, wb, pc, t, wrow2, ntb2, lane);
    __syncthreads();   // H overwrite vs lagging readers
    EPI8(
        float2 bb = ldsf2(smb+BIAS_OFF+B1_B + col*4);
        __half2 hh = __floats2half2_rn(gelu_f(c0v + bb.x), gelu_f(c1v + bb.y));
        sts32u(haddr(smb, row, col), *(u32*)&hh);
    );

    // ---------------- h = gelu(h1 @ W2 + b2) ----------------
    #pragma unroll
    for (int i = 0; i < 16; i++) for (int j = 0; j < 4; j++) acc2[i][j] = 0.0f;
    gemmT<8>(smb+H_OFF, 256, 4, g_tape+T_W2, g_tape+T_SCAN, acc2, wb, pc, t, wrow2, ntb2, lane);
    __syncthreads();
    EPI8(
        float2 bb = ldsf2(smb+BIAS_OFF+B2_B + col*4);
        __half2 hh = __floats2half2_rn(gelu_f(c0v + bb.x), gelu_f(c1v + bb.y));
        sts32u(haddr(smb, row, col), *(u32*)&hh);
    );

    // ---------------- 48-step scan ----------------
    #pragma unroll 1
    for (int step = 0; step < Tn; step++){
        #pragma unroll 1
        for (int s = 0; s < 4; s++){
            const __half* g1s = g_tape + T_SCAN + (size_t)s*65536;
            const __half* g2s = g1s + 32768;
            float acc1[8][4];
            #pragma unroll
            for (int i = 0; i < 8; i++) for (int j = 0; j < 4; j++) acc1[i][j] = 0.0f;
            gemmT<4>(smb+H_OFF, 256, 2, g1s, g2s, acc1, wb, pc, t, wrow1, ntb1, lane);
            // G1 epi: g = gelu(. + bf1 slice) -> G region (fp16)
            #pragma unroll
            for (int mt = 0; mt < 2; mt++)
            #pragma unroll
            for (int hi = 0; hi < 2; hi++)
            #pragma unroll
            for (int nt = 0; nt < 4; nt++){
                int row = wrow1 + mt*16 + hi*8 + rl;
                int col = wcol1 + nt*8 + cl;
                float2 bb = ldsf2(smb+BIAS_OFF+BF1_B + (s*128+col)*4);
                __half2 hh = __floats2half2_rn(gelu_f(acc1[mt*4+nt][hi*2+0] + bb.x),
                                               gelu_f(acc1[mt*4+nt][hi*2+1] + bb.y));
                sts32u(gaddr(smb, row, col), *(u32*)&hh);
            }
            if (s == 0){
                #pragma unroll
                for (int i = 0; i < 16; i++) for (int j = 0; j < 4; j++) acc2[i][j] = 0.0f;
            }
            const __half* nxt = (s < 3) ? (g_tape + T_SCAN + (size_t)(s+1)*65536)
                               : (step < Tn-1 ? g_tape + T_SCAN : g_tape + T_WO);
            gemmT<8>(smb+G_OFF, 128, 2, g2s, nxt, acc2, wb, pc, t, wrow2, ntb2, lane);
        }
        // blend epi: u = tanh(. + bf2); h = 0.5h + 0.5u
        EPI8(
            float2 bb = ldsf2(smb+BIAS_OFF+BF2_B + col*4);
            float u0 = tanh_f(c0v + bb.x);
            float u1 = tanh_f(c1v + bb.y);
            u32 ha = haddr(smb, row, col);
            u32 ob = lds32u(ha);
            float2 of = __half22float2(*(__half2*)&ob);
            __half2 hh = __floats2half2_rn(0.5f*of.x + 0.5f*u0, 0.5f*of.y + 0.5f*u1);
            sts32u(ha, *(u32*)&hh);
        );
    }

    // ---------------- final: out = h @ Wo + bo ----------------
    #pragma unroll
    for (int i = 0; i < 16; i++) for (int j = 0; j < 4; j++) acc2[i][j] = 0.0f;
    gemmT<8>(smb+H_OFF, 256, 4, g_tape+T_WO, g_tape+T_W1, acc2, wb, pc, t, wrow2, ntb2, lane);
    EPI8(
        float2 bb = ldsf2(smb+BIAS_OFF+BO_B + col*4);
        float2 vv = make_float2(c0v + bb.x, c1v + bb.y);
        *(float2*)&out[(size_t)(r0+row)*256 + col] = vv;
    );
    cp_wait0();
}

extern "C" void kernel_launch(void* const* d_in, const int* in_sizes, int n_in,
                              void* d_out, int out_size)
{
    (void)out_size;
    const float *x=0,*z=0,*tbl=0,*W1=0,*b1=0,*W2=0,*b2=0,*Wf1=0,*bf1=0,*Wf2=0,*bf2=0,*Wo=0,*bo=0,*frq=0;
    const int* res=0;
    int c65536=0, c131072=0, c256=0;
    for (int i = 0; i < n_in; i++){
        const void* p = d_in[i];
        switch (in_sizes[i]){
            case 16384:   x   = (const float*)p; break;
            case 524288:  z   = (const float*)p; break;
            case 1048576: tbl = (const float*)p; break;
            case 41216:   W1  = (const float*)p; break;
            case 512:     bf1 = (const float*)p; break;
            case 8:       res = (const int*)p;   break;
            case 32:      frq = (const float*)p; break;
            case 65536:   if (c65536++  == 0) W2  = (const float*)p; else Wo  = (const float*)p; break;
            case 131072:  if (c131072++ == 0) Wf1 = (const float*)p; else Wf2 = (const float*)p; break;
            case 256:
                switch (c256++){
                    case 0: b1 = (const float*)p; break;
                    case 1: b2 = (const float*)p; break;
                    case 2: bf2 = (const float*)p; break;
                    default: bo = (const float*)p; break;
                }
                break;
            default: break;
        }
    }
    float* out = (float*)d_out;

    prep_tape<<<(NTAPE + 255)/256, 256>>>(W1, W2, Wf1, Wf2, Wo);

    cudaFuncSetAttribute(fractal_h16, cudaFuncAttributeMaxDynamicSharedMemorySize, SMEM_BYTES);
    fractal_h16<<<Bn/MROWS, NTHR, SMEM_BYTES>>>(x, z, tbl, b1, b2, bf1, bf2, bo, res, frq, out);
}